// round 10
// baseline (speedup 1.0000x reference)
#include <cuda_runtime.h>
#include <cuda_fp16.h>
#include <cstdint>

#define N_NODES 100000
#define E_EDGES 1600000
#define IN_DIM  128
#define KH      8
#define DH      16
#define F       128
#define NEG_SLOPE 0.2f
#define SCAN_B  1024
#define NBLK    ((N_NODES + SCAN_B - 1) / SCAN_B)   // 98
#define CAP     128

// ---------------- scratch ----------------
__device__ __half g_feat_h[N_NODES * F];
__device__ float  g_el[N_NODES * KH];
__device__ float  g_er[N_NODES * KH];
__device__ int    g_deg[N_NODES];
__device__ int    g_off[N_NODES + 1];
__device__ int    g_rank[E_EDGES];
__device__ int    g_psrc[E_EDGES];
__device__ unsigned long long g_desc[NBLK];   // hi32: status, lo32: value (zeroed at load & by scatter)

// ---------------- tf32 helpers ----------------
__device__ __forceinline__ void mma_tf32(float* c, const unsigned* a, const unsigned* b) {
    asm volatile("mma.sync.aligned.m16n8k8.row.col.f32.tf32.tf32.f32 "
        "{%0,%1,%2,%3}, {%4,%5,%6,%7}, {%8,%9}, {%0,%1,%2,%3};"
        : "+f"(c[0]), "+f"(c[1]), "+f"(c[2]), "+f"(c[3])
        : "r"(a[0]), "r"(a[1]), "r"(a[2]), "r"(a[3]), "r"(b[0]), "r"(b[1]));
}
__device__ __forceinline__ uint2 tf32_split(float x) {
    unsigned h, l;
    asm("cvt.rna.tf32.f32 %0, %1;" : "=r"(h) : "f"(x));
    float hf = __uint_as_float(h);
    asm("cvt.rna.tf32.f32 %0, %1;" : "=r"(l) : "f"(x - hf));
    return make_uint2(h, l);
}

// ---------------- P1: tf32 tensor GEMM feat @ W + fused el/er + fp16 store
__global__ __launch_bounds__(256) void gemm_kernel(const float* __restrict__ feat,
                                                   const float* __restrict__ W,
                                                   const float* __restrict__ attn_l,
                                                   const float* __restrict__ attn_r) {
    __shared__ uint2 sA[128][20];    // [row][k in chunk16], {hi,lo}, pad->conflict-free
    __shared__ uint2 sWt[16][132];   // [k][n]
    const int t    = threadIdx.x;
    const int lane = t & 31;
    const int wid  = t >> 5;
    const int wm   = wid >> 2;        // 0..1 : 64-row half
    const int wn   = wid & 3;         // 0..3 : 32-col quarter
    const int gtid = lane >> 2;
    const int tig  = lane & 3;
    const int row0 = blockIdx.x * 128;

    // global-load mapping (chunk = 128 rows x 16 k of feat; 16 k x 128 n of W)
    const int fr0 = t >> 2,        fc0 = t & 3;
    const int fr1 = (t + 256) >> 2, fc1 = (t + 256) & 3;
    const int wr0 = t >> 5,        wc0 = t & 31;
    const int wr1 = (t + 256) >> 5, wc1 = (t + 256) & 31;
    int gfr0 = row0 + fr0; if (gfr0 >= N_NODES) gfr0 = N_NODES - 1;
    int gfr1 = row0 + fr1; if (gfr1 >= N_NODES) gfr1 = N_NODES - 1;

    float4 fv0 = *(const float4*)&feat[gfr0 * IN_DIM + fc0 * 4];
    float4 fv1 = *(const float4*)&feat[gfr1 * IN_DIM + fc1 * 4];
    float4 wv0 = *(const float4*)&W[wr0 * F + wc0 * 4];
    float4 wv1 = *(const float4*)&W[wr1 * F + wc1 * 4];

    float cacc[4][4][4];
#pragma unroll
    for (int m = 0; m < 4; m++)
#pragma unroll
        for (int n = 0; n < 4; n++)
#pragma unroll
            for (int q = 0; q < 4; q++) cacc[m][n][q] = 0.f;

#pragma unroll
    for (int ch = 0; ch < 8; ch++) {
        // stage (split) prefetched regs -> smem
        sA[fr0][fc0 * 4 + 0] = tf32_split(fv0.x);
        sA[fr0][fc0 * 4 + 1] = tf32_split(fv0.y);
        sA[fr0][fc0 * 4 + 2] = tf32_split(fv0.z);
        sA[fr0][fc0 * 4 + 3] = tf32_split(fv0.w);
        sA[fr1][fc1 * 4 + 0] = tf32_split(fv1.x);
        sA[fr1][fc1 * 4 + 1] = tf32_split(fv1.y);
        sA[fr1][fc1 * 4 + 2] = tf32_split(fv1.z);
        sA[fr1][fc1 * 4 + 3] = tf32_split(fv1.w);
        sWt[wr0][wc0 * 4 + 0] = tf32_split(wv0.x);
        sWt[wr0][wc0 * 4 + 1] = tf32_split(wv0.y);
        sWt[wr0][wc0 * 4 + 2] = tf32_split(wv0.z);
        sWt[wr0][wc0 * 4 + 3] = tf32_split(wv0.w);
        sWt[wr1][wc1 * 4 + 0] = tf32_split(wv1.x);
        sWt[wr1][wc1 * 4 + 1] = tf32_split(wv1.y);
        sWt[wr1][wc1 * 4 + 2] = tf32_split(wv1.z);
        sWt[wr1][wc1 * 4 + 3] = tf32_split(wv1.w);
        __syncthreads();

        if (ch < 7) {   // prefetch next chunk
            int kb = (ch + 1) * 16;
            fv0 = *(const float4*)&feat[gfr0 * IN_DIM + kb + fc0 * 4];
            fv1 = *(const float4*)&feat[gfr1 * IN_DIM + kb + fc1 * 4];
            wv0 = *(const float4*)&W[(kb + wr0) * F + wc0 * 4];
            wv1 = *(const float4*)&W[(kb + wr1) * F + wc1 * 4];
        }

#pragma unroll
        for (int ks = 0; ks < 16; ks += 8) {
            unsigned bh[4][2], bl[4][2];
#pragma unroll
            for (int nt = 0; nt < 4; nt++) {
                int n = wn * 32 + nt * 8 + gtid;
                uint2 b0 = sWt[ks + tig][n];
                uint2 b1 = sWt[ks + tig + 4][n];
                bh[nt][0] = b0.x; bl[nt][0] = b0.y;
                bh[nt][1] = b1.x; bl[nt][1] = b1.y;
            }
#pragma unroll
            for (int mt = 0; mt < 4; mt++) {
                int r = wm * 64 + mt * 16 + gtid;
                uint2 a0 = sA[r][ks + tig];
                uint2 a1 = sA[r + 8][ks + tig];
                uint2 a2 = sA[r][ks + tig + 4];
                uint2 a3 = sA[r + 8][ks + tig + 4];
                unsigned ah[4] = {a0.x, a1.x, a2.x, a3.x};
                unsigned av[4] = {a0.y, a1.y, a2.y, a3.y};
#pragma unroll
                for (int nt = 0; nt < 4; nt++) {
                    mma_tf32(cacc[mt][nt], ah, bh[nt]);
                    mma_tf32(cacc[mt][nt], av, bh[nt]);
                    mma_tf32(cacc[mt][nt], ah, bl[nt]);
                }
            }
        }
        __syncthreads();
    }

    // epilogue: fp16 store + per-head el/er dots
    float alc[4][2], arc[4][2];
#pragma unroll
    for (int nt = 0; nt < 4; nt++)
#pragma unroll
        for (int c = 0; c < 2; c++) {
            int col = wn * 32 + nt * 8 + tig * 2 + c;   // col == head*16 + d
            alc[nt][c] = attn_l[col];
            arc[nt][c] = attn_r[col];
        }
#pragma unroll
    for (int mt = 0; mt < 4; mt++)
#pragma unroll
        for (int h = 0; h < 2; h++) {
            int node = row0 + wm * 64 + mt * 16 + h * 8 + gtid;
            bool ok = node < N_NODES;
#pragma unroll
            for (int nt = 0; nt < 4; nt++) {
                float v0 = cacc[mt][nt][h * 2 + 0];
                float v1 = cacc[mt][nt][h * 2 + 1];
                if (ok)
                    *(__half2*)&g_feat_h[node * F + wn * 32 + nt * 8 + tig * 2] =
                        __floats2half2_rn(v0, v1);
            }
#pragma unroll
            for (int j = 0; j < 2; j++) {          // 2 heads per warp quarter
                float pl = 0.f, pr = 0.f;
#pragma unroll
                for (int q = 0; q < 2; q++) {
                    int nt = 2 * j + q;
                    float v0 = cacc[mt][nt][h * 2 + 0];
                    float v1 = cacc[mt][nt][h * 2 + 1];
                    pl += v0 * alc[nt][0] + v1 * alc[nt][1];
                    pr += v0 * arc[nt][0] + v1 * arc[nt][1];
                }
                pl += __shfl_xor_sync(0xffffffffu, pl, 1);
                pl += __shfl_xor_sync(0xffffffffu, pl, 2);
                pr += __shfl_xor_sync(0xffffffffu, pr, 1);
                pr += __shfl_xor_sync(0xffffffffu, pr, 2);
                if (ok && tig == 0) {
                    int head = wn * 2 + j;
                    g_el[node * KH + head] = pl;
                    g_er[node * KH + head] = pr;
                }
            }
        }
}

// ---------------- CSR build (rank-based, self-resetting) ----------------
__global__ void hist_kernel(const int* __restrict__ dst) {
    int e = blockIdx.x * blockDim.x + threadIdx.x;
    if (e >= E_EDGES) return;
    g_rank[e] = atomicAdd(&g_deg[dst[e]], 1);
}

__device__ __forceinline__ unsigned long long desc_ld(int idx) {
    unsigned long long v;
    asm volatile("ld.volatile.global.u64 %0, [%1];" : "=l"(v) : "l"(&g_desc[idx]));
    return v;
}
__device__ __forceinline__ void desc_st(int idx, unsigned long long v) {
    asm volatile("st.volatile.global.u64 [%0], %1;" :: "l"(&g_desc[idx]), "l"(v) : "memory");
}

__global__ __launch_bounds__(SCAN_B) void scan_kernel() {
    __shared__ int warp_sums[32];
    __shared__ int s_bprefix;
    int tid  = threadIdx.x;
    int lane = tid & 31;
    int wid  = tid >> 5;
    int b    = blockIdx.x;
    int gid  = b * SCAN_B + tid;
    int v = (gid < N_NODES) ? g_deg[gid] : 0;
    if (gid < N_NODES) g_deg[gid] = 0;            // reset for next replay

    int x = v;
#pragma unroll
    for (int d = 1; d < 32; d <<= 1) {
        int tv = __shfl_up_sync(0xffffffffu, x, d);
        if (lane >= d) x += tv;
    }
    if (lane == 31) warp_sums[wid] = x;
    __syncthreads();
    if (wid == 0) {
        int y = warp_sums[lane];
#pragma unroll
        for (int d = 1; d < 32; d <<= 1) {
            int tv = __shfl_up_sync(0xffffffffu, y, d);
            if (lane >= d) y += tv;
        }
        warp_sums[lane] = y;
    }
    __syncthreads();
    int block_total = warp_sums[31];
    int excl = ((wid > 0) ? warp_sums[wid - 1] : 0) + x - v;

    if (wid == 0) {
        if (b == 0) {
            if (lane == 0) {
                desc_st(0, (2ULL << 32) | (unsigned)block_total);
                s_bprefix = 0;
            }
        } else {
            if (lane == 0) desc_st(b, (1ULL << 32) | (unsigned)block_total);
            int prefix = 0;
            int look = b - 1;
            while (look >= 0) {
                int idx = look - lane;
                unsigned long long d = 0;
                if (idx >= 0) {
                    do { d = desc_ld(idx); } while ((d >> 32) == 0ULL);
                }
                unsigned st = (idx >= 0) ? (unsigned)(d >> 32) : 0u;
                unsigned mask2 = __ballot_sync(0xffffffffu, st == 2u);
                int stop = mask2 ? (__ffs(mask2) - 1) : 32;
                int contrib = (idx >= 0 && lane <= stop) ? (int)(d & 0xffffffffULL) : 0;
#pragma unroll
                for (int dd = 16; dd > 0; dd >>= 1)
                    contrib += __shfl_xor_sync(0xffffffffu, contrib, dd);
                prefix += contrib;
                if (mask2) break;
                look -= 32;
            }
            if (lane == 0) {
                desc_st(b, (2ULL << 32) | (unsigned)(prefix + block_total));
                s_bprefix = prefix;
            }
        }
    }
    __syncthreads();
    if (gid < N_NODES) g_off[gid] = s_bprefix + excl;
    if (b == 0 && tid == 0) g_off[N_NODES] = E_EDGES;
}

__global__ void scatter_kernel(const int* __restrict__ src,
                               const int* __restrict__ dst) {
    int e = blockIdx.x * blockDim.x + threadIdx.x;
    if (blockIdx.x == 0 && threadIdx.x < NBLK) g_desc[threadIdx.x] = 0ULL;  // reset
    if (e >= E_EDGES) return;
    g_psrc[g_off[dst[e]] + g_rank[e]] = src[e];
}

// ---------------- P3: single-pass warp-per-dst gather ----------------
__device__ __forceinline__ void edge_math(float elv, float er_k,
                                          unsigned long long pk,
                                          float4& acc, float& ssum) {
    float v = elv + er_k;
    v = (v > 0.f) ? v : NEG_SLOPE * v;
    float ex = __expf(v);
    ssum += ex;
    __half2 h0 = ((const __half2*)&pk)[0];
    __half2 h1 = ((const __half2*)&pk)[1];
    float2 f0 = __half22float2(h0);
    float2 f1 = __half22float2(h1);
    acc.x = fmaf(ex, f0.x, acc.x);
    acc.y = fmaf(ex, f0.y, acc.y);
    acc.z = fmaf(ex, f1.x, acc.z);
    acc.w = fmaf(ex, f1.y, acc.w);
}

__global__ __launch_bounds__(256) void agg_csr_kernel(float* __restrict__ out) {
    __shared__ int s_src[8][CAP];
    int wid  = threadIdx.x >> 5;
    int lane = threadIdx.x & 31;
    int w = blockIdx.x * 8 + wid;
    if (w >= N_NODES) return;
    int off0 = g_off[w];
    int off1 = g_off[w + 1];
    int deg  = off1 - off0;
    int cached = (deg < CAP) ? deg : CAP;

    for (int i = lane; i < cached; i += 32) s_src[wid][i] = g_psrc[off0 + i];

    int khead = lane >> 2;
    float er_k = __ldg(&g_er[w * KH + khead]);
    __syncwarp();

    float4 acc = make_float4(0.f, 0.f, 0.f, 0.f);
    float ssum = 0.f;
    int i = 0;
    for (; i + 7 < cached; i += 8) {
        int s[8];
#pragma unroll
        for (int j = 0; j < 8; j++) s[j] = s_src[wid][i + j];
        float elv[8];
        unsigned long long pk[8];
#pragma unroll
        for (int j = 0; j < 8; j++) elv[j] = __ldg(&g_el[s[j] * KH + khead]);
#pragma unroll
        for (int j = 0; j < 8; j++)
            pk[j] = *(const unsigned long long*)&g_feat_h[s[j] * F + lane * 4];
#pragma unroll
        for (int j = 0; j < 8; j++) edge_math(elv[j], er_k, pk[j], acc, ssum);
    }
    for (; i < cached; i++) {
        int s = s_src[wid][i];
        float elv = __ldg(&g_el[s * KH + khead]);
        unsigned long long pk = *(const unsigned long long*)&g_feat_h[s * F + lane * 4];
        edge_math(elv, er_k, pk, acc, ssum);
    }
    for (; i < deg; i++) {
        int s = g_psrc[off0 + i];
        float elv = __ldg(&g_el[s * KH + khead]);
        unsigned long long pk = *(const unsigned long long*)&g_feat_h[s * F + lane * 4];
        edge_math(elv, er_k, pk, acc, ssum);
    }

    float inv = (deg > 0) ? __fdividef(1.f, ssum) : 0.f;
    *(float4*)&out[w * F + lane * 4] =
        make_float4(acc.x * inv, acc.y * inv, acc.z * inv, acc.w * inv);
}

// ---------------- launch ----------------
extern "C" void kernel_launch(void* const* d_in, const int* in_sizes, int n_in,
                              void* d_out, int out_size) {
    const float* feat   = (const float*)d_in[0];
    const float* W      = (const float*)d_in[1];
    const float* attn_l = (const float*)d_in[2];
    const float* attn_r = (const float*)d_in[3];
    const int*   src    = (const int*)d_in[4];
    const int*   dst    = (const int*)d_in[5];
    float* out = (float*)d_out;

    static cudaStream_t s2 = nullptr;
    static cudaEvent_t evFork = nullptr, evCsr = nullptr;
    if (s2 == nullptr) {
        cudaStreamCreateWithFlags(&s2, cudaStreamNonBlocking);
        cudaEventCreateWithFlags(&evFork, cudaEventDisableTiming);
        cudaEventCreateWithFlags(&evCsr, cudaEventDisableTiming);
    }

    const int T = 256;
    cudaEventRecord(evFork, 0);
    cudaStreamWaitEvent(s2, evFork, 0);
    hist_kernel<<<(E_EDGES + T - 1) / T, T, 0, s2>>>(dst);
    scan_kernel<<<NBLK, SCAN_B, 0, s2>>>();
    scatter_kernel<<<(E_EDGES + T - 1) / T, T, 0, s2>>>(src, dst);
    cudaEventRecord(evCsr, s2);

    gemm_kernel<<<(N_NODES + 127) / 128, T>>>(feat, W, attn_l, attn_r);

    cudaStreamWaitEvent(0, evCsr, 0);
    agg_csr_kernel<<<(N_NODES + 7) / 8, T>>>(out);
}

// round 11
// speedup vs baseline: 1.1623x; 1.1623x over previous
#include <cuda_runtime.h>
#include <cuda_fp16.h>
#include <cstdint>

#define N_NODES 100000
#define E_EDGES 1600000
#define IN_DIM  128
#define KH      8
#define DH      16
#define F       128
#define NEG_SLOPE 0.2f
#define SCAN_B  1024
#define NBLK    ((N_NODES + SCAN_B - 1) / SCAN_B)   // 98
#define CAP     128

// ---------------- scratch ----------------
__device__ __half g_feat_h[N_NODES * F];
__device__ float  g_el[N_NODES * KH];
__device__ float  g_er[N_NODES * KH];
__device__ int    g_deg[N_NODES];
__device__ int    g_off[N_NODES + 1];
__device__ int    g_rank[E_EDGES];
__device__ int    g_psrc[E_EDGES];
__device__ unsigned long long g_desc[NBLK];

// ---------------- P1: GEMM feat @ W (row-pair FFMA2, reg-pipelined) -------
#define BM 64
#define BK 32
__global__ __launch_bounds__(256) void gemm_kernel(const float* __restrict__ feat,
                                                   const float* __restrict__ W,
                                                   const float* __restrict__ attn_l,
                                                   const float* __restrict__ attn_r) {
    __shared__ __align__(16) float sXT[BK][BM + 4];
    __shared__ __align__(16) float sW[BK][F];
    const int row0 = blockIdx.x * BM;
    const int t  = threadIdx.x;
    const int tx = t & 31;
    const int ty = t >> 5;
    const int head = tx >> 2;
    const int sub  = tx & 3;

    float4 al = *(const float4*)&attn_l[head * DH + sub * 4];
    float4 ar = *(const float4*)&attn_r[head * DH + sub * 4];

    const int xr_  = (t) >> 3,        xc_  = (t) & 7;
    const int xr2_ = (t + 256) >> 3,  xc2_ = (t + 256) & 7;
    int gxr  = row0 + xr_;  if (gxr  >= N_NODES) gxr  = N_NODES - 1;
    int gxr2 = row0 + xr2_; if (gxr2 >= N_NODES) gxr2 = N_NODES - 1;

    float4 xv0, xv1, wv0, wv1, wv2, wv3;
    xv0 = *(const float4*)&feat[gxr  * IN_DIM + 0 + xc_  * 4];
    xv1 = *(const float4*)&feat[gxr2 * IN_DIM + 0 + xc2_ * 4];
    {
        int r0_ = t >> 5, c0_ = t & 31;
        wv0 = *(const float4*)&W[(0 + r0_ +  0) * F + c0_ * 4];
        wv1 = *(const float4*)&W[(0 + r0_ +  8) * F + c0_ * 4];
        wv2 = *(const float4*)&W[(0 + r0_ + 16) * F + c0_ * 4];
        wv3 = *(const float4*)&W[(0 + r0_ + 24) * F + c0_ * 4];
    }

    unsigned long long acc2[4][4];
#pragma unroll
    for (int p = 0; p < 4; p++)
#pragma unroll
        for (int c = 0; c < 4; c++) acc2[p][c] = 0ULL;

#pragma unroll
    for (int it = 0; it < IN_DIM / BK; it++) {
        sXT[xc_  * 4 + 0][xr_]  = xv0.x;
        sXT[xc_  * 4 + 1][xr_]  = xv0.y;
        sXT[xc_  * 4 + 2][xr_]  = xv0.z;
        sXT[xc_  * 4 + 3][xr_]  = xv0.w;
        sXT[xc2_ * 4 + 0][xr2_] = xv1.x;
        sXT[xc2_ * 4 + 1][xr2_] = xv1.y;
        sXT[xc2_ * 4 + 2][xr2_] = xv1.z;
        sXT[xc2_ * 4 + 3][xr2_] = xv1.w;
        {
            int r0_ = t >> 5, c0_ = t & 31;
            *(float4*)&sW[r0_ +  0][c0_ * 4] = wv0;
            *(float4*)&sW[r0_ +  8][c0_ * 4] = wv1;
            *(float4*)&sW[r0_ + 16][c0_ * 4] = wv2;
            *(float4*)&sW[r0_ + 24][c0_ * 4] = wv3;
        }
        __syncthreads();

        if (it + 1 < IN_DIM / BK) {
            int k0n = (it + 1) * BK;
            xv0 = *(const float4*)&feat[gxr  * IN_DIM + k0n + xc_  * 4];
            xv1 = *(const float4*)&feat[gxr2 * IN_DIM + k0n + xc2_ * 4];
            int r0_ = t >> 5, c0_ = t & 31;
            wv0 = *(const float4*)&W[(k0n + r0_ +  0) * F + c0_ * 4];
            wv1 = *(const float4*)&W[(k0n + r0_ +  8) * F + c0_ * 4];
            wv2 = *(const float4*)&W[(k0n + r0_ + 16) * F + c0_ * 4];
            wv3 = *(const float4*)&W[(k0n + r0_ + 24) * F + c0_ * 4];
        }

#pragma unroll
        for (int kk = 0; kk < BK; kk++) {
            float4 wv = *(const float4*)&sW[kk][tx * 4];
            float4 xa = *(const float4*)&sXT[kk][ty * 8];
            float4 xb = *(const float4*)&sXT[kk][ty * 8 + 4];
            unsigned long long xp[4], wd[4];
            asm("mov.b64 %0, {%1, %2};" : "=l"(xp[0]) : "f"(xa.x), "f"(xa.y));
            asm("mov.b64 %0, {%1, %2};" : "=l"(xp[1]) : "f"(xa.z), "f"(xa.w));
            asm("mov.b64 %0, {%1, %2};" : "=l"(xp[2]) : "f"(xb.x), "f"(xb.y));
            asm("mov.b64 %0, {%1, %2};" : "=l"(xp[3]) : "f"(xb.z), "f"(xb.w));
            asm("mov.b64 %0, {%1, %1};" : "=l"(wd[0]) : "f"(wv.x));
            asm("mov.b64 %0, {%1, %1};" : "=l"(wd[1]) : "f"(wv.y));
            asm("mov.b64 %0, {%1, %1};" : "=l"(wd[2]) : "f"(wv.z));
            asm("mov.b64 %0, {%1, %1};" : "=l"(wd[3]) : "f"(wv.w));
#pragma unroll
            for (int p = 0; p < 4; p++)
#pragma unroll
                for (int c = 0; c < 4; c++)
                    asm("fma.rn.f32x2 %0, %1, %2, %3;"
                        : "=l"(acc2[p][c]) : "l"(xp[p]), "l"(wd[c]), "l"(acc2[p][c]));
        }
        __syncthreads();
    }

    float accf[8][4];
#pragma unroll
    for (int p = 0; p < 4; p++)
#pragma unroll
        for (int c = 0; c < 4; c++)
            asm("mov.b64 {%0, %1}, %2;"
                : "=f"(accf[2 * p][c]), "=f"(accf[2 * p + 1][c]) : "l"(acc2[p][c]));

#pragma unroll
    for (int r = 0; r < 8; r++) {
        int gr = row0 + ty * 8 + r;
        float a0 = accf[r][0], a1 = accf[r][1], a2 = accf[r][2], a3 = accf[r][3];
        float pl = a0 * al.x + a1 * al.y + a2 * al.z + a3 * al.w;
        float pr = a0 * ar.x + a1 * ar.y + a2 * ar.z + a3 * ar.w;
        pl += __shfl_xor_sync(0xffffffffu, pl, 1);
        pl += __shfl_xor_sync(0xffffffffu, pl, 2);
        pr += __shfl_xor_sync(0xffffffffu, pr, 1);
        pr += __shfl_xor_sync(0xffffffffu, pr, 2);
        if (gr < N_NODES) {
            __half2* hp = (__half2*)&g_feat_h[gr * F + tx * 4];
            hp[0] = __floats2half2_rn(a0, a1);
            hp[1] = __floats2half2_rn(a2, a3);
            if (sub == 0) {
                g_el[gr * KH + head] = pl;
                g_er[gr * KH + head] = pr;
            }
        }
    }
}

// ---------------- CSR build (rank-based, self-resetting) ----------------
__global__ void hist_kernel(const int* __restrict__ dst) {
    int e = blockIdx.x * blockDim.x + threadIdx.x;
    if (e >= E_EDGES) return;
    g_rank[e] = atomicAdd(&g_deg[dst[e]], 1);
}

__device__ __forceinline__ unsigned long long desc_ld(int idx) {
    unsigned long long v;
    asm volatile("ld.volatile.global.u64 %0, [%1];" : "=l"(v) : "l"(&g_desc[idx]));
    return v;
}
__device__ __forceinline__ void desc_st(int idx, unsigned long long v) {
    asm volatile("st.volatile.global.u64 [%0], %1;" :: "l"(&g_desc[idx]), "l"(v) : "memory");
}

__global__ __launch_bounds__(SCAN_B) void scan_kernel() {
    __shared__ int warp_sums[32];
    __shared__ int s_bprefix;
    int tid  = threadIdx.x;
    int lane = tid & 31;
    int wid  = tid >> 5;
    int b    = blockIdx.x;
    int gid  = b * SCAN_B + tid;
    int v = (gid < N_NODES) ? g_deg[gid] : 0;
    if (gid < N_NODES) g_deg[gid] = 0;            // reset for next replay

    int x = v;
#pragma unroll
    for (int d = 1; d < 32; d <<= 1) {
        int tv = __shfl_up_sync(0xffffffffu, x, d);
        if (lane >= d) x += tv;
    }
    if (lane == 31) warp_sums[wid] = x;
    __syncthreads();
    if (wid == 0) {
        int y = warp_sums[lane];
#pragma unroll
        for (int d = 1; d < 32; d <<= 1) {
            int tv = __shfl_up_sync(0xffffffffu, y, d);
            if (lane >= d) y += tv;
        }
        warp_sums[lane] = y;
    }
    __syncthreads();
    int block_total = warp_sums[31];
    int excl = ((wid > 0) ? warp_sums[wid - 1] : 0) + x - v;

    if (wid == 0) {
        if (b == 0) {
            if (lane == 0) {
                desc_st(0, (2ULL << 32) | (unsigned)block_total);
                s_bprefix = 0;
            }
        } else {
            if (lane == 0) desc_st(b, (1ULL << 32) | (unsigned)block_total);
            int prefix = 0;
            int look = b - 1;
            while (look >= 0) {
                int idx = look - lane;
                unsigned long long d = 0;
                if (idx >= 0) {
                    do { d = desc_ld(idx); } while ((d >> 32) == 0ULL);
                }
                unsigned st = (idx >= 0) ? (unsigned)(d >> 32) : 0u;
                unsigned mask2 = __ballot_sync(0xffffffffu, st == 2u);
                int stop = mask2 ? (__ffs(mask2) - 1) : 32;
                int contrib = (idx >= 0 && lane <= stop) ? (int)(d & 0xffffffffULL) : 0;
#pragma unroll
                for (int dd = 16; dd > 0; dd >>= 1)
                    contrib += __shfl_xor_sync(0xffffffffu, contrib, dd);
                prefix += contrib;
                if (mask2) break;
                look -= 32;
            }
            if (lane == 0) {
                desc_st(b, (2ULL << 32) | (unsigned)(prefix + block_total));
                s_bprefix = prefix;
            }
        }
    }
    __syncthreads();
    if (gid < N_NODES) g_off[gid] = s_bprefix + excl;
    if (b == 0 && tid == 0) g_off[N_NODES] = E_EDGES;
}

__global__ void scatter_kernel(const int* __restrict__ src,
                               const int* __restrict__ dst) {
    int e = blockIdx.x * blockDim.x + threadIdx.x;
    if (blockIdx.x == 0 && threadIdx.x < NBLK) g_desc[threadIdx.x] = 0ULL;  // reset
    if (e >= E_EDGES) return;
    g_psrc[g_off[dst[e]] + g_rank[e]] = src[e];
}

// ---------------- P3: single-pass warp-per-dst gather ----------------
__device__ __forceinline__ void edge_math(float elv, float er_k,
                                          unsigned long long pk,
                                          float4& acc, float& ssum) {
    float v = elv + er_k;
    v = (v > 0.f) ? v : NEG_SLOPE * v;
    float ex = __expf(v);
    ssum += ex;
    __half2 h0 = ((const __half2*)&pk)[0];
    __half2 h1 = ((const __half2*)&pk)[1];
    float2 f0 = __half22float2(h0);
    float2 f1 = __half22float2(h1);
    acc.x = fmaf(ex, f0.x, acc.x);
    acc.y = fmaf(ex, f0.y, acc.y);
    acc.z = fmaf(ex, f1.x, acc.z);
    acc.w = fmaf(ex, f1.y, acc.w);
}

#define AGG_T 512
__global__ __launch_bounds__(AGG_T) void agg_csr_kernel(float* __restrict__ out) {
    __shared__ int s_src[AGG_T / 32][CAP];
    int wid  = threadIdx.x >> 5;
    int lane = threadIdx.x & 31;
    int w = blockIdx.x * (AGG_T / 32) + wid;
    if (w >= N_NODES) return;
    int off0 = g_off[w];
    int off1 = g_off[w + 1];
    int deg  = off1 - off0;
    int cached = (deg < CAP) ? deg : CAP;

    for (int i = lane; i < cached; i += 32) s_src[wid][i] = __ldg(&g_psrc[off0 + i]);

    int khead = lane >> 2;
    float er_k = __ldg(&g_er[w * KH + khead]);
    __syncwarp();

    float4 acc = make_float4(0.f, 0.f, 0.f, 0.f);
    float ssum = 0.f;
    int i = 0;
    for (; i + 7 < cached; i += 8) {
        int s[8];
#pragma unroll
        for (int j = 0; j < 8; j++) s[j] = s_src[wid][i + j];
        float elv[8];
        unsigned long long pk[8];
#pragma unroll
        for (int j = 0; j < 8; j++) elv[j] = __ldg(&g_el[s[j] * KH + khead]);
#pragma unroll
        for (int j = 0; j < 8; j++)
            pk[j] = *(const unsigned long long*)&g_feat_h[s[j] * F + lane * 4];
#pragma unroll
        for (int j = 0; j < 8; j++) edge_math(elv[j], er_k, pk[j], acc, ssum);
    }
    for (; i < cached; i++) {
        int s = s_src[wid][i];
        float elv = __ldg(&g_el[s * KH + khead]);
        unsigned long long pk = *(const unsigned long long*)&g_feat_h[s * F + lane * 4];
        edge_math(elv, er_k, pk, acc, ssum);
    }
    for (; i < deg; i++) {
        int s = __ldg(&g_psrc[off0 + i]);
        float elv = __ldg(&g_el[s * KH + khead]);
        unsigned long long pk = *(const unsigned long long*)&g_feat_h[s * F + lane * 4];
        edge_math(elv, er_k, pk, acc, ssum);
    }

    float inv = (deg > 0) ? __fdividef(1.f, ssum) : 0.f;
    *(float4*)&out[w * F + lane * 4] =
        make_float4(acc.x * inv, acc.y * inv, acc.z * inv, acc.w * inv);
}

// ---------------- launch (CSR chain overlapped with GEMM) ----------------
extern "C" void kernel_launch(void* const* d_in, const int* in_sizes, int n_in,
                              void* d_out, int out_size) {
    const float* feat   = (const float*)d_in[0];
    const float* W      = (const float*)d_in[1];
    const float* attn_l = (const float*)d_in[2];
    const float* attn_r = (const float*)d_in[3];
    const int*   src    = (const int*)d_in[4];
    const int*   dst    = (const int*)d_in[5];
    float* out = (float*)d_out;

    static cudaStream_t s2 = nullptr;
    static cudaEvent_t evFork = nullptr, evCsr = nullptr;
    if (s2 == nullptr) {
        cudaStreamCreateWithFlags(&s2, cudaStreamNonBlocking);
        cudaEventCreateWithFlags(&evFork, cudaEventDisableTiming);
        cudaEventCreateWithFlags(&evCsr, cudaEventDisableTiming);
    }

    const int T = 256;
    cudaEventRecord(evFork, 0);
    cudaStreamWaitEvent(s2, evFork, 0);
    hist_kernel<<<(E_EDGES + T - 1) / T, T, 0, s2>>>(dst);
    scan_kernel<<<NBLK, SCAN_B, 0, s2>>>();
    scatter_kernel<<<(E_EDGES + T - 1) / T, T, 0, s2>>>(src, dst);
    cudaEventRecord(evCsr, s2);

    gemm_kernel<<<(N_NODES + BM - 1) / BM, T>>>(feat, W, attn_l, attn_r);

    cudaStreamWaitEvent(0, evCsr, 0);
    agg_csr_kernel<<<(N_NODES + (AGG_T / 32) - 1) / (AGG_T / 32), AGG_T>>>(out);
}